// round 8
// baseline (speedup 1.0000x reference)
#include <cuda_runtime.h>

// LZC48: out[t] = 6-bit MSB-first float encoding of the index of the first
// nonzero among X[t*48 .. t*48+47]; 48 (0b110000) if all zero. Inputs are
// exact {0.0f, 1.0f} floats, so bit-level integer logic is exact (rel_err=0).
//
// R2/R3 finding: probe requests 32B/word but DRAM sees ~116B/word ->
// consistent with 128B line-granular fetch (probes touch 2 of every 3 lines;
// 1 line/word is the floor for ANY layout since adjacent probe sectors live
// in distinct lines). The only lever below that floor is sector-granular
// fill: probe with ld.global.cv (__ldcv, fetch-fresh / no-allocate).
// If it fills 32B sectors: reads ~244 MB -> 67-134 MB. Zero data reuse, so
// bypassing caches costs nothing. (5th submission of this A/B; rounds 4-7
// never acquired a GPU.)
//
// Writes stay smem-staged: block's 6144B output slab written as 384 coalesced
// 128B-aligned STG.128 (R3: +3%, occ 91%).

__global__ __launch_bounds__(256) void lzc48_kernel(
    const uint4* __restrict__ X, float4* __restrict__ out4, int n_words)
{
    __shared__ float s[256 * 6];            // 6 KB

    int t = blockIdx.x * 256 + threadIdx.x;

    int lzc = 48;
    if (t < n_words) {
        const uint4* p = X + (size_t)t * 12;    // 48 floats = 12 uint4
        uint4 v0 = __ldcv(p);                   // bits 0..3  (bytes [0,16))
        uint4 v1 = __ldcv(p + 1);               // bits 4..7  (bytes [16,32))

        // Branchless first-set-bit over bits 0..7; smallest index applied
        // last wins.
        if (v1.w != 0u) lzc = 7;
        if (v1.z != 0u) lzc = 6;
        if (v1.y != 0u) lzc = 5;
        if (v1.x != 0u) lzc = 4;
        if (v0.w != 0u) lzc = 3;
        if (v0.z != 0u) lzc = 2;
        if (v0.y != 0u) lzc = 1;
        if (v0.x != 0u) lzc = 0;

        if (lzc == 48) {                    // cold path: prob 2^-8 per thread
            #pragma unroll 1
            for (int j = 2; j < 12; j++) {
                uint4 v = __ldcv(p + j);
                int base = j * 4;
                int l = 48;
                if (v.w != 0u) l = base + 3;
                if (v.z != 0u) l = base + 2;
                if (v.y != 0u) l = base + 1;
                if (v.x != 0u) l = base;
                if (l != 48) { lzc = l; break; }
            }
            // lzc stays 48 (0b110000) for an all-zero word.
        }
    }

    // 6-bit MSB-first encoding into smem (LOP3 + SEL, no I2F).
    float* sp = s + threadIdx.x * 6;
    sp[0] = (lzc & 32) ? 1.0f : 0.0f;
    sp[1] = (lzc & 16) ? 1.0f : 0.0f;
    sp[2] = (lzc &  8) ? 1.0f : 0.0f;
    sp[3] = (lzc &  4) ? 1.0f : 0.0f;
    sp[4] = (lzc &  2) ? 1.0f : 0.0f;
    sp[5] = (lzc &  1) ? 1.0f : 0.0f;
    __syncthreads();

    // Write the block's 6144B output slab (128B-aligned) as 384 float4s —
    // every DRAM sector/line fully covered by coalesced STG.128.
    long long total_floats = (long long)n_words * 6;
    long long blk_base_f   = (long long)blockIdx.x * 1536;   // floats
    long long blk_floats   = total_floats - blk_base_f;      // <=1536 in tail

    const float4* s4 = (const float4*)s;
    if (blk_floats >= 1536) {
        float4* o = out4 + blockIdx.x * 384;
        #pragma unroll
        for (int i = 0; i < 2; i++) {
            int idx = threadIdx.x + i * 256;
            if (idx < 384) __stcs(o + idx, s4[idx]);
        }
    } else if (blk_floats > 0) {
        // Tail block (not hit for the benchmark shape): scalar stores.
        float* o = (float*)out4 + blk_base_f;
        for (int i = threadIdx.x; i < (int)blk_floats; i += 256)
            o[i] = s[i];
    }
}

extern "C" void kernel_launch(void* const* d_in, const int* in_sizes, int n_in,
                              void* d_out, int out_size)
{
    const float* X = (const float*)d_in[0];
    int n_words = in_sizes[0] / 48;          // 1024*2048 = 2,097,152
    int blocks = (n_words + 255) / 256;      // 8192
    lzc48_kernel<<<blocks, 256>>>((const uint4*)X, (float4*)d_out, n_words);
}